// round 5
// baseline (speedup 1.0000x reference)
#include <cuda_runtime.h>
#include <cuda_bf16.h>
#include <math.h>

#define NSPAT (64*64*64)
#define OFFSETS_OFF (2*5*NSPAT)
#define LOSS_OFF (16*NSPAT)

// 134MB scratch: featT[b][z][y][x][0:64]=bf16 hi, [64:128]=bf16 lo
__device__ __align__(16) __nv_bfloat16 g_featT[(size_t)2*64*64*64*128];
// B fragments: [tap(27)][kc(4)][lane(32)] -> uint4 {bh0,bh1,bl0,bl1}
__device__ __align__(16) uint4 g_btab[3456];
__device__ unsigned long long g_key[128];
__device__ double g_loss[1];
__device__ unsigned g_tile;

// ---------------------------------------------------------------------------
// Pass 1: NCDHW fp32 -> NHWC bf16 hi/lo
// ---------------------------------------------------------------------------
__global__ __launch_bounds__(256) void transpose_kernel(const float* __restrict__ feat) {
    __shared__ float s[64][65];
    int y = blockIdx.x, z = blockIdx.y, b = blockIdx.z;
    int tid = threadIdx.x;
    const float* base = feat + (size_t)b * 64 * NSPAT + z * 4096 + y * 64;
    for (int i = tid; i < 4096; i += 256) {
        int c = i >> 6, x = i & 63;
        s[c][x] = base[(size_t)c * NSPAT + x];
    }
    __syncthreads();
    __nv_bfloat16* dst = g_featT + ((((size_t)b * 64 + z) * 64 + y) * 64) * 128;
    for (int i = tid; i < 4096; i += 256) {
        int v = i >> 6, c = i & 63;
        float val = s[c][v];
        __nv_bfloat16 hi = __float2bfloat16(val);
        __nv_bfloat16 lo = __float2bfloat16(val - __bfloat162float(hi));
        dst[v * 128 + c]      = hi;
        dst[v * 128 + 64 + c] = lo;
    }
}

// ---------------------------------------------------------------------------
// Precompute packed B fragments once
// ---------------------------------------------------------------------------
__global__ void build_tab_kernel(const float* __restrict__ cls_w,
                                 const float* __restrict__ off_w) {
    int i = blockIdx.x * 256 + threadIdx.x;     // 0..3455
    if (i >= 3456) return;
    int l = i & 31, kc = (i >> 5) & 3, tap = i >> 7;
    int n = l >> 2, k0 = (l & 3) * 2;
    int kk = kc * 16 + k0;
    const float* w = (n < 5) ? (cls_w + n * 1728) : (off_w + (n - 5) * 1728);
    float w0 = w[kk * 27 + tap],       w1 = w[(kk + 1) * 27 + tap];
    float w8 = w[(kk + 8) * 27 + tap], w9 = w[(kk + 9) * 27 + tap];
    float l0 = w0 - __bfloat162float(__float2bfloat16(w0));
    float l1 = w1 - __bfloat162float(__float2bfloat16(w1));
    float l8 = w8 - __bfloat162float(__float2bfloat16(w8));
    float l9 = w9 - __bfloat162float(__float2bfloat16(w9));
    uint4 r;
    r.x = (unsigned)__bfloat16_as_ushort(__float2bfloat16(w0))
        | ((unsigned)__bfloat16_as_ushort(__float2bfloat16(w1)) << 16);
    r.y = (unsigned)__bfloat16_as_ushort(__float2bfloat16(w8))
        | ((unsigned)__bfloat16_as_ushort(__float2bfloat16(w9)) << 16);
    r.z = (unsigned)__bfloat16_as_ushort(__float2bfloat16(l0))
        | ((unsigned)__bfloat16_as_ushort(__float2bfloat16(l1)) << 16);
    r.w = (unsigned)__bfloat16_as_ushort(__float2bfloat16(l8))
        | ((unsigned)__bfloat16_as_ushort(__float2bfloat16(l9)) << 16);
    g_btab[i] = r;
}

// ---------------------------------------------------------------------------
// Pass 2: persistent work-stealing implicit-GEMM conv, 2z x 4y tiles
// ---------------------------------------------------------------------------
__device__ __forceinline__ void writeOut(float* out, int b, int n, int m, float v) {
    if (n < 5) out[(size_t)(b * 5 + n) * NSPAT + m] = v;
    else       out[OFFSETS_OFF + (size_t)(b * 3 + (n - 5)) * NSPAT + m] = v;
}

#define MMA_B16(ac, a0,a1,a2,a3, b0,b1) \
    asm volatile("mma.sync.aligned.m16n8k16.row.col.f32.bf16.bf16.f32 " \
        "{%0,%1,%2,%3}, {%4,%5,%6,%7}, {%8,%9}, {%0,%1,%2,%3};" \
        : "+f"(ac[0]), "+f"(ac[1]), "+f"(ac[2]), "+f"(ac[3]) \
        : "r"(a0), "r"(a1), "r"(a2), "r"(a3), "r"(b0), "r"(b1))

#define SM_BUF 16896
#define SM_TOTAL (3*SM_BUF + 16)
#define NTILES 1024

extern __shared__ unsigned char s_dyn[];

__global__ __launch_bounds__(256, 4) void conv_mma_kernel(
        const float* __restrict__ cls_b, const float* __restrict__ off_b,
        float* __restrict__ out) {
    int tid = threadIdx.x, lane = tid & 31, warp = tid >> 5;
    int q = warp & 3, riL = warp >> 2;

    unsigned sbase = (unsigned)__cvta_generic_to_shared(s_dyn);
    unsigned* s_tile = (unsigned*)(s_dyn + 3 * SM_BUF);

    // zero x-halo voxels (v=0,65) in all 3 buffers — persists across tiles
    if (tid < 96) {
        int bb = tid >> 5, idx = tid & 31;
        int v = (idx < 16) ? 0 : 65, ch = idx & 15;
        ((uint4*)(s_dyn + bb * SM_BUF))[v * 16 + ch] = make_uint4(0, 0, 0, 0);
    }

    int n0 = (lane & 3) * 2;
    float bi0 = (n0 < 5)     ? cls_b[n0]     : off_b[n0 - 5];
    float bi1 = (n0 + 1 < 5) ? cls_b[n0 + 1] : off_b[n0 - 4];

    for (;;) {
        if (tid == 0) s_tile[0] = atomicAdd(&g_tile, 1u);
        __syncthreads();                 // broadcast ticket; also fences prev tile's smem use
        unsigned t = s_tile[0];
        if (t >= NTILES) break;

        int z0 = (t & 31) * 2;
        int y0 = ((t >> 5) & 15) * 4;
        int b  = t >> 9;

        int zzlo = (z0 == 0) ? 1 : 0, zzhi = (z0 == 62) ? 2 : 3;
        int yylo = (y0 == 0) ? 1 : 0, yyhi = (y0 == 60) ? 4 : 5;
        int ny = yyhi - yylo + 1;
        int nrow = (zzhi - zzlo + 1) * ny;

        float acc[4][4];
#pragma unroll
        for (int s = 0; s < 4; s++) { acc[s][0]=bi0; acc[s][1]=bi1; acc[s][2]=bi0; acc[s][3]=bi1; }

#define ISSUE_LOAD(I_, BUF_) do { \
    int zz_ = zzlo + (I_) / ny, yy_ = yylo + (I_) % ny; \
    const uint4* src_ = (const uint4*)(g_featT + \
        ((((size_t)b * 64 + (z0 + zz_ - 1)) * 64 + (y0 + yy_ - 1)) * 64) * 128); \
    unsigned dbase_ = sbase + (BUF_) * SM_BUF; \
    _Pragma("unroll") \
    for (int k_ = 0; k_ < 4; k_++) { \
        int i_ = tid + k_ * 256; int v_ = (i_ >> 4) + 1, ch_ = i_ & 15; \
        unsigned d_ = dbase_ + (unsigned)((v_ * 16 + (ch_ ^ (v_ & 7))) * 16); \
        asm volatile("cp.async.cg.shared.global [%0], [%1], 16;" :: "r"(d_), "l"(src_ + i_)); \
    } \
    asm volatile("cp.async.commit_group;"); \
} while (0)

        ISSUE_LOAD(0, 0);
        ISSUE_LOAD(1, 1);

        for (int i = 0; i < nrow; i++) {
            if (i + 1 < nrow) asm volatile("cp.async.wait_group 1;");
            else              asm volatile("cp.async.wait_group 0;");
            __syncthreads();             // single barrier per row
            if (i + 2 < nrow) ISSUE_LOAD(i + 2, (i + 2) % 3);

            int zz = zzlo + i / ny, yy = yylo + i % ny;
            bool active = (riL == 0) ? (yy <= 4) : (yy >= 1);
            if (active) {
                unsigned abase = sbase + (unsigned)((i % 3) * SM_BUF);
#pragma unroll
                for (int dx = 0; dx < 3; dx++) {
#pragma unroll
                    for (int kc = 0; kc < 4; kc++) {
                        int vs = 16 * q + dx + (lane & 15);
                        int chunk = 2 * kc + (lane >> 4);
                        unsigned aAddr = abase + (unsigned)((vs * 16 + (chunk ^ (vs & 7))) * 16);
                        unsigned ah0, ah1, ah2, ah3, al0, al1, al2, al3;
                        asm volatile("ldmatrix.sync.aligned.m8n8.x4.shared.b16 {%0,%1,%2,%3}, [%4];"
                            : "=r"(ah0), "=r"(ah1), "=r"(ah2), "=r"(ah3) : "r"(aAddr));
                        asm volatile("ldmatrix.sync.aligned.m8n8.x4.shared.b16 {%0,%1,%2,%3}, [%4];"
                            : "=r"(al0), "=r"(al1), "=r"(al2), "=r"(al3) : "r"(aAddr + 128));
#pragma unroll
                        for (int zi = 0; zi < 2; zi++) {
                            int dzt = zz - zi;
                            if ((unsigned)dzt > 2u) continue;
#pragma unroll
                            for (int rih = 0; rih < 2; rih++) {
                                int ri = rih * 2 + riL;
                                int dyt = yy - ri;
                                if ((unsigned)dyt > 2u) continue;
                                int tap = (dzt * 3 + dyt) * 3 + dx;
                                uint4 B = __ldg(&g_btab[(tap * 4 + kc) * 32 + lane]);
                                MMA_B16(acc[zi * 2 + rih], ah0, ah1, ah2, ah3, B.x, B.y);
                                MMA_B16(acc[zi * 2 + rih], ah0, ah1, ah2, ah3, B.z, B.w);
                                MMA_B16(acc[zi * 2 + rih], al0, al1, al2, al3, B.x, B.y);
                            }
                        }
                    }
                }
            }
        }
        __syncthreads();                 // all compute done before next tile's loads

#pragma unroll
        for (int s = 0; s < 4; s++) {
            int zi = s >> 1, ri = (s & 1) * 2 + riL;
            int mg = (z0 + zi) * 4096 + (y0 + ri) * 64 + 16 * q + (lane >> 2);
            writeOut(out, b, n0,     mg,     acc[s][0]);
            writeOut(out, b, n0 + 1, mg,     acc[s][1]);
            writeOut(out, b, n0,     mg + 8, acc[s][2]);
            writeOut(out, b, n0 + 1, mg + 8, acc[s][3]);
        }
    }
}

// ---------------------------------------------------------------------------
// Best anchor per GT: argmin(d) with u64 (d_bits<<32|idx) atomicMin
// ---------------------------------------------------------------------------
__global__ void init_kernel() {
    int t = threadIdx.x;
    if (t < 128) g_key[t] = 0xFFFFFFFFFFFFFFFFull;
    if (t == 128) g_loss[0] = 0.0;
    if (t == 129) g_tile = 0u;
}

__global__ __launch_bounds__(256) void best_anchor_kernel(const float* __restrict__ out,
                                                          const float* __restrict__ labels) {
    int b = blockIdx.y, tid = threadIdx.x, lane = tid & 31, warp = tid >> 5;
    int base = blockIdx.x * 1024;
    const float* off = out + OFFSETS_OFF + (size_t)b * 3 * NSPAT;

    float pz[4], py[4], px[4];
#pragma unroll
    for (int i = 0; i < 4; i++) {
        int m = base + i * 256 + tid;
        int zc = m >> 12, yc = (m >> 6) & 63, xc = m & 63;
        pz[i] = (zc + 0.5f) * 32.f + off[m];
        py[i] = (yc + 0.5f) * 32.f + off[NSPAT + m];
        px[i] = (xc + 0.5f) * 32.f + off[2 * NSPAT + m];
    }
    __shared__ float sc[3][64];
    __shared__ unsigned long long s_red[64][8];
    if (tid < 192) { int d = tid >> 6, n = tid & 63; sc[d][n] = labels[(b * 5 + d) * 64 + n]; }
    __syncthreads();

    for (int n = 0; n < 64; n++) {
        float tz = sc[0][n], ty = sc[1][n], tx = sc[2][n];
        unsigned long long best = 0xFFFFFFFFFFFFFFFFull;
#pragma unroll
        for (int i = 0; i < 4; i++) {
            float dz = pz[i] - tz, dy = py[i] - ty, dx = px[i] - tx;
            float d = dz * dz + dy * dy + dx * dx;
            unsigned long long key = ((unsigned long long)__float_as_uint(d) << 32)
                                   | (unsigned)(base + i * 256 + tid);
            best = min(best, key);
        }
#pragma unroll
        for (int s = 16; s; s >>= 1)
            best = min(best, __shfl_down_sync(0xFFFFFFFFu, best, s));
        if (lane == 0) s_red[n][warp] = best;
    }
    __syncthreads();
    if (tid < 64) {
        unsigned long long best = s_red[tid][0];
#pragma unroll
        for (int w = 1; w < 8; w++) best = min(best, s_red[tid][w]);
        atomicMin(&g_key[b * 64 + tid], best);
    }
}

// ---------------------------------------------------------------------------
// Focal + reg loss (fast-math transcendentals; double accumulation)
// ---------------------------------------------------------------------------
__device__ __forceinline__ float logsig_f(float x) {
    return fminf(x, 0.f) - __logf(1.f + __expf(-fabsf(x)));
}

__global__ __launch_bounds__(256) void loss_kernel(const float* __restrict__ out,
                                                   const float* __restrict__ labels) {
    int b = blockIdx.y, tid = threadIdx.x;
    int m0 = blockIdx.x * 256, m = m0 + tid;

    __shared__ int   s_match[256];
    __shared__ float s_gt0[4];
    s_match[tid] = -1;
    __syncthreads();
    if (tid < 64) {
        float c = labels[(b * 5 + 3) * 64 + tid];
        if (c >= -0.5f) {
            int bm = (int)(unsigned)(g_key[b * 64 + tid] & 0xFFFFFFFFull);
            if (bm >= m0 && bm < m0 + 256) atomicMax(&s_match[bm - m0], tid);
        }
    }
    if (tid == 128) {
        float sg = labels[(b * 5 + 4) * 64];
        s_gt0[0] = labels[(b * 5 + 0) * 64];
        s_gt0[1] = labels[(b * 5 + 1) * 64];
        s_gt0[2] = labels[(b * 5 + 2) * 64];
        s_gt0[3] = 1.f / (2.f * sg * sg);
    }
    __syncthreads();

    int matched = s_match[tid];
    int assigned = (matched >= 0) ? (int)labels[(b * 5 + 3) * 64 + matched] : -1;

    const float* lg = out + (size_t)b * 5 * NSPAT;
    float csum = 0.f;
#pragma unroll
    for (int c = 0; c < 5; c++) {
        float x = lg[(size_t)c * NSPAT + m];
        float p = 1.f / (1.f + __expf(-x));
        if (c == assigned) { float qq = 1.f - p; csum -= qq * qq * logsig_f(x); }
        else               {                     csum -= p * p * logsig_f(-x); }
    }

    float r = 0.f;
    if (matched < 0) {
        const float* off = out + OFFSETS_OFF + (size_t)b * 3 * NSPAT;
        int z = m >> 12, y = (m >> 6) & 63, x = m & 63;
        float pz = (z + 0.5f) * 32.f + off[m];
        float py = (y + 0.5f) * 32.f + off[NSPAT + m];
        float px = (x + 0.5f) * 32.f + off[2 * NSPAT + m];
        float dz = pz - s_gt0[0], dy = py - s_gt0[1], dx = px - s_gt0[2];
        float d = dz * dz + dy * dy + dx * dx;
        r = 1.f - __expf(-d * s_gt0[3]);
    }

    __shared__ double sd[256];
    sd[tid] = (double)csum + (double)r;
    __syncthreads();
    for (int s = 128; s > 0; s >>= 1) {
        if (tid < s) sd[tid] += sd[tid + s];
        __syncthreads();
    }
    if (tid == 0) atomicAdd(&g_loss[0], sd[0]);
}

__global__ void finalize_kernel(const void* __restrict__ nitems, float* __restrict__ out) {
    long long iv = ((const int*)nitems)[0];
    float     fv = ((const float*)nitems)[0];
    double n = (iv >= 1 && iv <= 1048576) ? (double)iv : (double)fv;
    out[LOSS_OFF] = (float)(g_loss[0] / n);
}

// ---------------------------------------------------------------------------
extern "C" void kernel_launch(void* const* d_in, const int* in_sizes, int n_in,
                              void* d_out, int out_size) {
    const float* feat   = (const float*)d_in[0];
    const float* labels = (const float*)d_in[1];
    const float* cls_w  = (const float*)d_in[2];
    const float* cls_b  = (const float*)d_in[3];
    const float* off_w  = (const float*)d_in[4];
    const float* off_b  = (const float*)d_in[5];
    float* out = (float*)d_out;

    cudaFuncSetAttribute(conv_mma_kernel, cudaFuncAttributeMaxDynamicSharedMemorySize, SM_TOTAL);

    transpose_kernel<<<dim3(64, 64, 2), 256>>>(feat);
    build_tab_kernel<<<14, 256>>>(cls_w, off_w);
    init_kernel<<<1, 256>>>();
    conv_mma_kernel<<<592, 256, SM_TOTAL>>>(cls_b, off_b, out);
    best_anchor_kernel<<<dim3(256, 2), 256>>>(out, labels);
    loss_kernel<<<dim3(1024, 2), 256>>>(out, labels);
    finalize_kernel<<<1, 1>>>(d_in[6], out);
}

// round 6
// speedup vs baseline: 1.3277x; 1.3277x over previous
#include <cuda_runtime.h>
#include <cuda_bf16.h>
#include <math.h>

#define NSPAT (64*64*64)
#define OFFSETS_OFF (2*5*NSPAT)
#define LOSS_OFF (16*NSPAT)

// padded scratch: featT[b][z+1 of 66][y+1 of 66][x of 64][0:64]=hi,[64:128]=lo
// pad rows are never written -> stay zero from static init
#define PD 66
__device__ __align__(16) __nv_bfloat16 g_featT[(size_t)2*PD*PD*64*128];
// B fragments: [tap(27)][kc(4)][lane(32)] -> uint4 {bh0,bh1,bl0,bl1}
__device__ __align__(16) uint4 g_btab[3456];
__device__ unsigned long long g_key[128];
__device__ double g_loss[1];
__device__ unsigned g_tile;

// ---------------------------------------------------------------------------
// Pass 1: NCDHW fp32 -> padded NHWC bf16 hi/lo
// ---------------------------------------------------------------------------
__global__ __launch_bounds__(256) void transpose_kernel(const float* __restrict__ feat) {
    __shared__ float s[64][65];
    int y = blockIdx.x, z = blockIdx.y, b = blockIdx.z;
    int tid = threadIdx.x;
    const float* base = feat + (size_t)b * 64 * NSPAT + z * 4096 + y * 64;
    for (int i = tid; i < 4096; i += 256) {
        int c = i >> 6, x = i & 63;
        s[c][x] = base[(size_t)c * NSPAT + x];
    }
    __syncthreads();
    __nv_bfloat16* dst = g_featT + ((((size_t)b * PD + z + 1) * PD + y + 1) * 64) * 128;
    for (int i = tid; i < 4096; i += 256) {
        int v = i >> 6, c = i & 63;
        float val = s[c][v];
        __nv_bfloat16 hi = __float2bfloat16(val);
        __nv_bfloat16 lo = __float2bfloat16(val - __bfloat162float(hi));
        dst[v * 128 + c]      = hi;
        dst[v * 128 + 64 + c] = lo;
    }
}

// ---------------------------------------------------------------------------
// Precompute packed B fragments once
// ---------------------------------------------------------------------------
__global__ void build_tab_kernel(const float* __restrict__ cls_w,
                                 const float* __restrict__ off_w) {
    int i = blockIdx.x * 256 + threadIdx.x;     // 0..3455
    if (i >= 3456) return;
    int l = i & 31, kc = (i >> 5) & 3, tap = i >> 7;
    int n = l >> 2, k0 = (l & 3) * 2;
    int kk = kc * 16 + k0;
    const float* w = (n < 5) ? (cls_w + n * 1728) : (off_w + (n - 5) * 1728);
    float w0 = w[kk * 27 + tap],       w1 = w[(kk + 1) * 27 + tap];
    float w8 = w[(kk + 8) * 27 + tap], w9 = w[(kk + 9) * 27 + tap];
    float l0 = w0 - __bfloat162float(__float2bfloat16(w0));
    float l1 = w1 - __bfloat162float(__float2bfloat16(w1));
    float l8 = w8 - __bfloat162float(__float2bfloat16(w8));
    float l9 = w9 - __bfloat162float(__float2bfloat16(w9));
    uint4 r;
    r.x = (unsigned)__bfloat16_as_ushort(__float2bfloat16(w0))
        | ((unsigned)__bfloat16_as_ushort(__float2bfloat16(w1)) << 16);
    r.y = (unsigned)__bfloat16_as_ushort(__float2bfloat16(w8))
        | ((unsigned)__bfloat16_as_ushort(__float2bfloat16(w9)) << 16);
    r.z = (unsigned)__bfloat16_as_ushort(__float2bfloat16(l0))
        | ((unsigned)__bfloat16_as_ushort(__float2bfloat16(l1)) << 16);
    r.w = (unsigned)__bfloat16_as_ushort(__float2bfloat16(l8))
        | ((unsigned)__bfloat16_as_ushort(__float2bfloat16(l9)) << 16);
    g_btab[i] = r;
}

// ---------------------------------------------------------------------------
// Pass 2: persistent implicit-GEMM conv, 2z x 4y tiles, fully static loops
// ---------------------------------------------------------------------------
__device__ __forceinline__ void writeOut(float* out, int b, int n, int m, float v) {
    if (n < 5) out[(size_t)(b * 5 + n) * NSPAT + m] = v;
    else       out[OFFSETS_OFF + (size_t)(b * 3 + (n - 5)) * NSPAT + m] = v;
}

#define MMA_B16(ac, a0,a1,a2,a3, b0,b1) \
    asm volatile("mma.sync.aligned.m16n8k16.row.col.f32.bf16.bf16.f32 " \
        "{%0,%1,%2,%3}, {%4,%5,%6,%7}, {%8,%9}, {%0,%1,%2,%3};" \
        : "+f"(ac[0]), "+f"(ac[1]), "+f"(ac[2]), "+f"(ac[3]) \
        : "r"(a0), "r"(a1), "r"(a2), "r"(a3), "r"(b0), "r"(b1))

#define SM_BUF 16896
#define SM_TAB (3*SM_BUF)
#define SM_TOTAL (SM_TAB + 55296 + 16)
#define NTILES 1024
#define NBLK 296

extern __shared__ unsigned char s_dyn[];

__global__ __launch_bounds__(256) void conv_mma_kernel(
        const float* __restrict__ cls_b, const float* __restrict__ off_b,
        float* __restrict__ out) {
    int tid = threadIdx.x, lane = tid & 31, warp = tid >> 5;
    int q = warp & 3, riL = warp >> 2;

    unsigned sbase = (unsigned)__cvta_generic_to_shared(s_dyn);
    const uint4* s_tab = (const uint4*)(s_dyn + SM_TAB);
    unsigned* s_tile = (unsigned*)(s_dyn + SM_TAB + 55296);

    // load B table once per block; zero x-halo voxels (v=0,65) in all buffers
    {
        uint4* dst = (uint4*)(s_dyn + SM_TAB);
        for (int i = tid; i < 3456; i += 256) dst[i] = g_btab[i];
    }
    if (tid < 96) {
        int bb = tid >> 5, idx = tid & 31;
        int v = (idx < 16) ? 0 : 65, ch = idx & 15;
        ((uint4*)(s_dyn + bb * SM_BUF))[v * 16 + ch] = make_uint4(0, 0, 0, 0);
    }

    int n0 = (lane & 3) * 2;
    float bi0 = (n0 < 5)     ? cls_b[n0]     : off_b[n0 - 5];
    float bi1 = (n0 + 1 < 5) ? cls_b[n0 + 1] : off_b[n0 - 4];

    for (;;) {
        if (tid == 0) s_tile[0] = atomicAdd(&g_tile, 1u);
        __syncthreads();                 // ticket broadcast; fences table + prev tile
        unsigned t = s_tile[0];
        if (t >= NTILES) break;

        int z0 = (t & 31) * 2;
        int y0 = ((t >> 5) & 15) * 4;
        int b  = t >> 9;

        float acc[4][4];
#pragma unroll
        for (int s = 0; s < 4; s++) { acc[s][0]=bi0; acc[s][1]=bi1; acc[s][2]=bi0; acc[s][3]=bi1; }

        // padded row address: z_in+1 = z0+zz, y_in+1 = y0+yy
#define ISSUE_LOAD(ZZ_, YY_, BUF_) do { \
    const uint4* src_ = (const uint4*)(g_featT + \
        ((((size_t)b * PD + (z0 + (ZZ_))) * PD + (y0 + (YY_))) * 64) * 128); \
    unsigned dbase_ = sbase + (BUF_) * SM_BUF; \
    _Pragma("unroll") \
    for (int k_ = 0; k_ < 4; k_++) { \
        int i_ = tid + k_ * 256; int v_ = (i_ >> 4) + 1, ch_ = i_ & 15; \
        unsigned d_ = dbase_ + (unsigned)((v_ * 16 + (ch_ ^ (v_ & 7))) * 16); \
        asm volatile("cp.async.cg.shared.global [%0], [%1], 16;" :: "r"(d_), "l"(src_ + i_)); \
    } \
    asm volatile("cp.async.commit_group;"); \
} while (0)

        ISSUE_LOAD(0, 0, 0);
        ISSUE_LOAD(0, 1, 1);

#pragma unroll 1
        for (int zz = 0; zz < 4; zz++) {
#pragma unroll
            for (int yy = 0; yy < 6; yy++) {
                if (zz == 3 && yy == 5) asm volatile("cp.async.wait_group 0;");
                else                    asm volatile("cp.async.wait_group 1;");
                __syncthreads();
                if (!(zz == 3 && yy >= 4)) {
                    if (yy < 4) ISSUE_LOAD(zz,     yy + 2, (yy + 2) % 3);
                    else        ISSUE_LOAD(zz + 1, yy - 4, (yy + 2) % 3);
                }

                bool active = riL ? (yy >= 1) : (yy <= 4);
                if (active) {
                    unsigned abase = sbase + (unsigned)((yy % 3) * SM_BUF);
#pragma unroll
                    for (int dx = 0; dx < 3; dx++) {
#pragma unroll
                        for (int kc = 0; kc < 4; kc++) {
                            int vs = 16 * q + dx + (lane & 15);
                            int chunk = 2 * kc + (lane >> 4);
                            unsigned aAddr = abase + (unsigned)((vs * 16 + (chunk ^ (vs & 7))) * 16);
                            unsigned ah0, ah1, ah2, ah3, al0, al1, al2, al3;
                            asm volatile("ldmatrix.sync.aligned.m8n8.x4.shared.b16 {%0,%1,%2,%3}, [%4];"
                                : "=r"(ah0), "=r"(ah1), "=r"(ah2), "=r"(ah3) : "r"(aAddr));
                            asm volatile("ldmatrix.sync.aligned.m8n8.x4.shared.b16 {%0,%1,%2,%3}, [%4];"
                                : "=r"(al0), "=r"(al1), "=r"(al2), "=r"(al3) : "r"(aAddr + 128));
#pragma unroll
                            for (int zi = 0; zi < 2; zi++) {
                                unsigned dz = (unsigned)(zz - zi);
                                if (dz > 2u) continue;          // uniform in zz-loop
#pragma unroll
                                for (int rih = 0; rih < 2; rih++) {
                                    int y = rih * 2 + riL;
                                    unsigned dy = (unsigned)(yy - y);
                                    if (dy > 2u) continue;      // warp-uniform, yy static
                                    int tap = (int)(dz * 9u + dy * 3u) + dx;
                                    uint4 B = s_tab[(tap * 4 + kc) * 32 + lane];
                                    MMA_B16(acc[zi * 2 + rih], ah0, ah1, ah2, ah3, B.x, B.y);
                                    MMA_B16(acc[zi * 2 + rih], ah0, ah1, ah2, ah3, B.z, B.w);
                                    MMA_B16(acc[zi * 2 + rih], al0, al1, al2, al3, B.x, B.y);
                                }
                            }
                        }
                    }
                }
            }
        }
        __syncthreads();                 // all reads done before next tile's loads

#pragma unroll
        for (int s = 0; s < 4; s++) {
            int zi = s >> 1, ri = (s & 1) * 2 + riL;
            int mg = (z0 + zi) * 4096 + (y0 + ri) * 64 + 16 * q + (lane >> 2);
            writeOut(out, b, n0,     mg,     acc[s][0]);
            writeOut(out, b, n0 + 1, mg,     acc[s][1]);
            writeOut(out, b, n0,     mg + 8, acc[s][2]);
            writeOut(out, b, n0 + 1, mg + 8, acc[s][3]);
        }
    }
}

// ---------------------------------------------------------------------------
// Best anchor per GT: argmin(d) with u64 (d_bits<<32|idx) atomicMin
// ---------------------------------------------------------------------------
__global__ void init_kernel() {
    int t = threadIdx.x;
    if (t < 128) g_key[t] = 0xFFFFFFFFFFFFFFFFull;
    if (t == 128) g_loss[0] = 0.0;
    if (t == 129) g_tile = 0u;
}

__global__ __launch_bounds__(256) void best_anchor_kernel(const float* __restrict__ out,
                                                          const float* __restrict__ labels) {
    int b = blockIdx.y, tid = threadIdx.x, lane = tid & 31, warp = tid >> 5;
    int base = blockIdx.x * 1024;
    const float* off = out + OFFSETS_OFF + (size_t)b * 3 * NSPAT;

    float pz[4], py[4], px[4];
#pragma unroll
    for (int i = 0; i < 4; i++) {
        int m = base + i * 256 + tid;
        int zc = m >> 12, yc = (m >> 6) & 63, xc = m & 63;
        pz[i] = (zc + 0.5f) * 32.f + off[m];
        py[i] = (yc + 0.5f) * 32.f + off[NSPAT + m];
        px[i] = (xc + 0.5f) * 32.f + off[2 * NSPAT + m];
    }
    __shared__ float sc[3][64];
    __shared__ unsigned long long s_red[64][8];
    if (tid < 192) { int d = tid >> 6, n = tid & 63; sc[d][n] = labels[(b * 5 + d) * 64 + n]; }
    __syncthreads();

    for (int n = 0; n < 64; n++) {
        float tz = sc[0][n], ty = sc[1][n], tx = sc[2][n];
        unsigned long long best = 0xFFFFFFFFFFFFFFFFull;
#pragma unroll
        for (int i = 0; i < 4; i++) {
            float dz = pz[i] - tz, dy = py[i] - ty, dx = px[i] - tx;
            float d = dz * dz + dy * dy + dx * dx;
            unsigned long long key = ((unsigned long long)__float_as_uint(d) << 32)
                                   | (unsigned)(base + i * 256 + tid);
            best = min(best, key);
        }
#pragma unroll
        for (int s = 16; s; s >>= 1)
            best = min(best, __shfl_down_sync(0xFFFFFFFFu, best, s));
        if (lane == 0) s_red[n][warp] = best;
    }
    __syncthreads();
    if (tid < 64) {
        unsigned long long best = s_red[tid][0];
#pragma unroll
        for (int w = 1; w < 8; w++) best = min(best, s_red[tid][w]);
        atomicMin(&g_key[b * 64 + tid], best);
    }
}

// ---------------------------------------------------------------------------
// Focal + reg loss (fast-math transcendentals; double accumulation)
// ---------------------------------------------------------------------------
__device__ __forceinline__ float logsig_f(float x) {
    return fminf(x, 0.f) - __logf(1.f + __expf(-fabsf(x)));
}

__global__ __launch_bounds__(256) void loss_kernel(const float* __restrict__ out,
                                                   const float* __restrict__ labels) {
    int b = blockIdx.y, tid = threadIdx.x;
    int m0 = blockIdx.x * 256, m = m0 + tid;

    __shared__ int   s_match[256];
    __shared__ float s_gt0[4];
    s_match[tid] = -1;
    __syncthreads();
    if (tid < 64) {
        float c = labels[(b * 5 + 3) * 64 + tid];
        if (c >= -0.5f) {
            int bm = (int)(unsigned)(g_key[b * 64 + tid] & 0xFFFFFFFFull);
            if (bm >= m0 && bm < m0 + 256) atomicMax(&s_match[bm - m0], tid);
        }
    }
    if (tid == 128) {
        float sg = labels[(b * 5 + 4) * 64];
        s_gt0[0] = labels[(b * 5 + 0) * 64];
        s_gt0[1] = labels[(b * 5 + 1) * 64];
        s_gt0[2] = labels[(b * 5 + 2) * 64];
        s_gt0[3] = 1.f / (2.f * sg * sg);
    }
    __syncthreads();

    int matched = s_match[tid];
    int assigned = (matched >= 0) ? (int)labels[(b * 5 + 3) * 64 + matched] : -1;

    const float* lg = out + (size_t)b * 5 * NSPAT;
    float csum = 0.f;
#pragma unroll
    for (int c = 0; c < 5; c++) {
        float x = lg[(size_t)c * NSPAT + m];
        float p = 1.f / (1.f + __expf(-x));
        if (c == assigned) { float qq = 1.f - p; csum -= qq * qq * logsig_f(x); }
        else               {                     csum -= p * p * logsig_f(-x); }
    }

    float r = 0.f;
    if (matched < 0) {
        const float* off = out + OFFSETS_OFF + (size_t)b * 3 * NSPAT;
        int z = m >> 12, y = (m >> 6) & 63, x = m & 63;
        float pz = (z + 0.5f) * 32.f + off[m];
        float py = (y + 0.5f) * 32.f + off[NSPAT + m];
        float px = (x + 0.5f) * 32.f + off[2 * NSPAT + m];
        float dz = pz - s_gt0[0], dy = py - s_gt0[1], dx = px - s_gt0[2];
        float d = dz * dz + dy * dy + dx * dx;
        r = 1.f - __expf(-d * s_gt0[3]);
    }

    __shared__ double sd[256];
    sd[tid] = (double)csum + (double)r;
    __syncthreads();
    for (int s = 128; s > 0; s >>= 1) {
        if (tid < s) sd[tid] += sd[tid + s];
        __syncthreads();
    }
    if (tid == 0) atomicAdd(&g_loss[0], sd[0]);
}

__global__ void finalize_kernel(const void* __restrict__ nitems, float* __restrict__ out) {
    long long iv = ((const int*)nitems)[0];
    float     fv = ((const float*)nitems)[0];
    double n = (iv >= 1 && iv <= 1048576) ? (double)iv : (double)fv;
    out[LOSS_OFF] = (float)(g_loss[0] / n);
}

// ---------------------------------------------------------------------------
extern "C" void kernel_launch(void* const* d_in, const int* in_sizes, int n_in,
                              void* d_out, int out_size) {
    const float* feat   = (const float*)d_in[0];
    const float* labels = (const float*)d_in[1];
    const float* cls_w  = (const float*)d_in[2];
    const float* cls_b  = (const float*)d_in[3];
    const float* off_w  = (const float*)d_in[4];
    const float* off_b  = (const float*)d_in[5];
    float* out = (float*)d_out;

    cudaFuncSetAttribute(conv_mma_kernel, cudaFuncAttributeMaxDynamicSharedMemorySize, SM_TOTAL);

    transpose_kernel<<<dim3(64, 64, 2), 256>>>(feat);
    build_tab_kernel<<<14, 256>>>(cls_w, off_w);
    init_kernel<<<1, 256>>>();
    conv_mma_kernel<<<NBLK, 256, SM_TOTAL>>>(cls_b, off_b, out);
    best_anchor_kernel<<<dim3(256, 2), 256>>>(out, labels);
    loss_kernel<<<dim3(1024, 2), 256>>>(out, labels);
    finalize_kernel<<<1, 1>>>(d_in[6], out);
}

// round 7
// speedup vs baseline: 1.9153x; 1.4425x over previous
#include <cuda_runtime.h>
#include <cuda_fp16.h>
#include <math.h>

#define NSPAT (64*64*64)
#define OFFSETS_OFF (2*5*NSPAT)
#define LOSS_OFF (16*NSPAT)

// padded scratch: featT[b][z+1 of 66][y+1 of 66][x of 64][c of 64] fp16
// pad rows never written -> stay zero from static init
#define PD 66
__device__ __align__(16) __half g_featT[(size_t)2*PD*PD*64*64];
// B fragments: [tap(27)][kc(4)][lane(32)] -> uint2 {b0,b1} fp16x2
__device__ __align__(16) uint2 g_btab[3456];
__device__ unsigned long long g_key[128];
__device__ double g_loss[1];
__device__ unsigned g_tile;

// ---------------------------------------------------------------------------
// Pass 1: NCDHW fp32 -> padded NHWC fp16
// ---------------------------------------------------------------------------
__global__ __launch_bounds__(256) void transpose_kernel(const float* __restrict__ feat) {
    __shared__ float s[64][65];
    int y = blockIdx.x, z = blockIdx.y, b = blockIdx.z;
    int tid = threadIdx.x;
    const float* base = feat + (size_t)b * 64 * NSPAT + z * 4096 + y * 64;
    for (int i = tid; i < 4096; i += 256) {
        int c = i >> 6, x = i & 63;
        s[c][x] = base[(size_t)c * NSPAT + x];
    }
    __syncthreads();
    __half* dst = g_featT + ((((size_t)b * PD + z + 1) * PD + y + 1) * 64) * 64;
    for (int i = tid; i < 4096; i += 256) {
        int v = i >> 6, c = i & 63;
        dst[v * 64 + c] = __float2half_rn(s[c][v]);
    }
}

// ---------------------------------------------------------------------------
// Precompute packed fp16 B fragments once
// ---------------------------------------------------------------------------
__global__ void build_tab_kernel(const float* __restrict__ cls_w,
                                 const float* __restrict__ off_w) {
    int i = blockIdx.x * 256 + threadIdx.x;     // 0..3455
    if (i >= 3456) return;
    int l = i & 31, kc = (i >> 5) & 3, tap = i >> 7;
    int n = l >> 2, k0 = (l & 3) * 2;
    int kk = kc * 16 + k0;
    const float* w = (n < 5) ? (cls_w + n * 1728) : (off_w + (n - 5) * 1728);
    uint2 r;
    r.x = (unsigned)__half_as_ushort(__float2half_rn(w[kk * 27 + tap]))
        | ((unsigned)__half_as_ushort(__float2half_rn(w[(kk + 1) * 27 + tap])) << 16);
    r.y = (unsigned)__half_as_ushort(__float2half_rn(w[(kk + 8) * 27 + tap]))
        | ((unsigned)__half_as_ushort(__float2half_rn(w[(kk + 9) * 27 + tap])) << 16);
    g_btab[i] = r;
}

// ---------------------------------------------------------------------------
// Pass 2: persistent fp16 implicit-GEMM conv, 2z x 4y tiles, static loops
// ---------------------------------------------------------------------------
__device__ __forceinline__ void writeOut(float* out, int b, int n, int m, float v) {
    if (n < 5) out[(size_t)(b * 5 + n) * NSPAT + m] = v;
    else       out[OFFSETS_OFF + (size_t)(b * 3 + (n - 5)) * NSPAT + m] = v;
}

#define MMA_F16(ac, a0,a1,a2,a3, b0,b1) \
    asm volatile("mma.sync.aligned.m16n8k16.row.col.f32.f16.f16.f32 " \
        "{%0,%1,%2,%3}, {%4,%5,%6,%7}, {%8,%9}, {%0,%1,%2,%3};" \
        : "+f"(ac[0]), "+f"(ac[1]), "+f"(ac[2]), "+f"(ac[3]) \
        : "r"(a0), "r"(a1), "r"(a2), "r"(a3), "r"(b0), "r"(b1))

#define SM_BUF 8448                 /* 66 voxels * 64ch * 2B */
#define SM_TAB (3*SM_BUF)
#define SM_TOTAL (SM_TAB + 27648 + 16)
#define NTILES 1024
#define NBLK 296

extern __shared__ unsigned char s_dyn[];

__global__ __launch_bounds__(256) void conv_mma_kernel(
        const float* __restrict__ cls_b, const float* __restrict__ off_b,
        float* __restrict__ out) {
    int tid = threadIdx.x, lane = tid & 31, warp = tid >> 5;
    int q = warp & 3, riL = warp >> 2;

    unsigned sbase = (unsigned)__cvta_generic_to_shared(s_dyn);
    const uint2* s_tab = (const uint2*)(s_dyn + SM_TAB);
    unsigned* s_tile = (unsigned*)(s_dyn + SM_TAB + 27648);

    // load B table; zero x-halo voxels (v=0,65) in all 3 buffers
    {
        uint2* dst = (uint2*)(s_dyn + SM_TAB);
        for (int i = tid; i < 3456; i += 256) dst[i] = g_btab[i];
    }
    if (tid < 48) {
        int bb = tid >> 4, idx = tid & 15;
        int v = (idx < 8) ? 0 : 65, ch = idx & 7;
        ((uint4*)(s_dyn + bb * SM_BUF))[v * 8 + ch] = make_uint4(0, 0, 0, 0);
    }

    int n0 = (lane & 3) * 2;
    float bi0 = (n0 < 5)     ? cls_b[n0]     : off_b[n0 - 5];
    float bi1 = (n0 + 1 < 5) ? cls_b[n0 + 1] : off_b[n0 - 4];

    for (;;) {
        if (tid == 0) s_tile[0] = atomicAdd(&g_tile, 1u);
        __syncthreads();                 // ticket broadcast; fences table + prev tile
        unsigned t = s_tile[0];
        if (t >= NTILES) break;

        int z0 = (t & 31) * 2;
        int y0 = ((t >> 5) & 15) * 4;
        int b  = t >> 9;

        float acc[4][4];
#pragma unroll
        for (int s = 0; s < 4; s++) { acc[s][0]=bi0; acc[s][1]=bi1; acc[s][2]=bi0; acc[s][3]=bi1; }

        // global row: 64 voxels * 128B = 512 uint4; smem voxels 1..64
#define ISSUE_LOAD(ZZ_, YY_, BUF_) do { \
    const uint4* src_ = (const uint4*)(g_featT + \
        ((((size_t)b * PD + (z0 + (ZZ_))) * PD + (y0 + (YY_))) * 64) * 64); \
    unsigned dbase_ = sbase + (BUF_) * SM_BUF; \
    _Pragma("unroll") \
    for (int k_ = 0; k_ < 2; k_++) { \
        int i_ = tid + k_ * 256; int v_ = (i_ >> 3) + 1, ch_ = i_ & 7; \
        unsigned d_ = dbase_ + (unsigned)((v_ * 8 + (ch_ ^ (v_ & 7))) * 16); \
        asm volatile("cp.async.cg.shared.global [%0], [%1], 16;" :: "r"(d_), "l"(src_ + i_)); \
    } \
    asm volatile("cp.async.commit_group;"); \
} while (0)

        ISSUE_LOAD(0, 0, 0);
        ISSUE_LOAD(0, 1, 1);

#pragma unroll 1
        for (int zz = 0; zz < 4; zz++) {
#pragma unroll
            for (int yy = 0; yy < 6; yy++) {
                if (zz == 3 && yy == 5) asm volatile("cp.async.wait_group 0;");
                else                    asm volatile("cp.async.wait_group 1;");
                __syncthreads();
                if (!(zz == 3 && yy >= 4)) {
                    if (yy < 4) ISSUE_LOAD(zz,     yy + 2, (yy + 2) % 3);
                    else        ISSUE_LOAD(zz + 1, yy - 4, (yy + 2) % 3);
                }

                bool active = riL ? (yy >= 1) : (yy <= 4);
                if (active) {
                    unsigned abase = sbase + (unsigned)((yy % 3) * SM_BUF);
#pragma unroll
                    for (int dx = 0; dx < 3; dx++) {
#pragma unroll
                        for (int kc = 0; kc < 4; kc++) {
                            int vs = 16 * q + dx + (lane & 15);
                            int chunk = 2 * kc + (lane >> 4);
                            unsigned aAddr = abase + (unsigned)((vs * 8 + (chunk ^ (vs & 7))) * 16);
                            unsigned a0, a1, a2, a3;
                            asm volatile("ldmatrix.sync.aligned.m8n8.x4.shared.b16 {%0,%1,%2,%3}, [%4];"
                                : "=r"(a0), "=r"(a1), "=r"(a2), "=r"(a3) : "r"(aAddr));
#pragma unroll
                            for (int zi = 0; zi < 2; zi++) {
                                unsigned dz = (unsigned)(zz - zi);
                                if (dz > 2u) continue;          // uniform in zz-loop
#pragma unroll
                                for (int rih = 0; rih < 2; rih++) {
                                    int y = rih * 2 + riL;
                                    unsigned dy = (unsigned)(yy - y);
                                    if (dy > 2u) continue;      // warp-uniform, yy static
                                    int tap = (int)(dz * 9u + dy * 3u) + dx;
                                    uint2 B = s_tab[(tap * 4 + kc) * 32 + lane];
                                    MMA_F16(acc[zi * 2 + rih], a0, a1, a2, a3, B.x, B.y);
                                }
                            }
                        }
                    }
                }
            }
        }
        __syncthreads();                 // all reads done before next tile's loads

#pragma unroll
        for (int s = 0; s < 4; s++) {
            int zi = s >> 1, ri = (s & 1) * 2 + riL;
            int mg = (z0 + zi) * 4096 + (y0 + ri) * 64 + 16 * q + (lane >> 2);
            writeOut(out, b, n0,     mg,     acc[s][0]);
            writeOut(out, b, n0 + 1, mg,     acc[s][1]);
            writeOut(out, b, n0,     mg + 8, acc[s][2]);
            writeOut(out, b, n0 + 1, mg + 8, acc[s][3]);
        }
    }
}

// ---------------------------------------------------------------------------
// Best anchor per GT: argmin(d) with u64 (d_bits<<32|idx) atomicMin
// ---------------------------------------------------------------------------
__global__ void init_kernel() {
    int t = threadIdx.x;
    if (t < 128) g_key[t] = 0xFFFFFFFFFFFFFFFFull;
    if (t == 128) g_loss[0] = 0.0;
    if (t == 129) g_tile = 0u;
}

__global__ __launch_bounds__(256) void best_anchor_kernel(const float* __restrict__ out,
                                                          const float* __restrict__ labels) {
    int b = blockIdx.y, tid = threadIdx.x, lane = tid & 31, warp = tid >> 5;
    int base = blockIdx.x * 1024;
    const float* off = out + OFFSETS_OFF + (size_t)b * 3 * NSPAT;

    float pz[4], py[4], px[4];
#pragma unroll
    for (int i = 0; i < 4; i++) {
        int m = base + i * 256 + tid;
        int zc = m >> 12, yc = (m >> 6) & 63, xc = m & 63;
        pz[i] = (zc + 0.5f) * 32.f + off[m];
        py[i] = (yc + 0.5f) * 32.f + off[NSPAT + m];
        px[i] = (xc + 0.5f) * 32.f + off[2 * NSPAT + m];
    }
    __shared__ float sc[3][64];
    __shared__ unsigned long long s_red[64][8];
    if (tid < 192) { int d = tid >> 6, n = tid & 63; sc[d][n] = labels[(b * 5 + d) * 64 + n]; }
    __syncthreads();

    for (int n = 0; n < 64; n++) {
        float tz = sc[0][n], ty = sc[1][n], tx = sc[2][n];
        unsigned long long best = 0xFFFFFFFFFFFFFFFFull;
#pragma unroll
        for (int i = 0; i < 4; i++) {
            float dz = pz[i] - tz, dy = py[i] - ty, dx = px[i] - tx;
            float d = dz * dz + dy * dy + dx * dx;
            unsigned long long key = ((unsigned long long)__float_as_uint(d) << 32)
                                   | (unsigned)(base + i * 256 + tid);
            best = min(best, key);
        }
#pragma unroll
        for (int s = 16; s; s >>= 1)
            best = min(best, __shfl_down_sync(0xFFFFFFFFu, best, s));
        if (lane == 0) s_red[n][warp] = best;
    }
    __syncthreads();
    if (tid < 64) {
        unsigned long long best = s_red[tid][0];
#pragma unroll
        for (int w = 1; w < 8; w++) best = min(best, s_red[tid][w]);
        atomicMin(&g_key[b * 64 + tid], best);
    }
}

// ---------------------------------------------------------------------------
// Focal + reg loss (fast-math transcendentals; double accumulation)
// ---------------------------------------------------------------------------
__device__ __forceinline__ float logsig_f(float x) {
    return fminf(x, 0.f) - __logf(1.f + __expf(-fabsf(x)));
}

__global__ __launch_bounds__(256) void loss_kernel(const float* __restrict__ out,
                                                   const float* __restrict__ labels) {
    int b = blockIdx.y, tid = threadIdx.x;
    int m0 = blockIdx.x * 256, m = m0 + tid;

    __shared__ int   s_match[256];
    __shared__ float s_gt0[4];
    s_match[tid] = -1;
    __syncthreads();
    if (tid < 64) {
        float c = labels[(b * 5 + 3) * 64 + tid];
        if (c >= -0.5f) {
            int bm = (int)(unsigned)(g_key[b * 64 + tid] & 0xFFFFFFFFull);
            if (bm >= m0 && bm < m0 + 256) atomicMax(&s_match[bm - m0], tid);
        }
    }
    if (tid == 128) {
        float sg = labels[(b * 5 + 4) * 64];
        s_gt0[0] = labels[(b * 5 + 0) * 64];
        s_gt0[1] = labels[(b * 5 + 1) * 64];
        s_gt0[2] = labels[(b * 5 + 2) * 64];
        s_gt0[3] = 1.f / (2.f * sg * sg);
    }
    __syncthreads();

    int matched = s_match[tid];
    int assigned = (matched >= 0) ? (int)labels[(b * 5 + 3) * 64 + matched] : -1;

    const float* lg = out + (size_t)b * 5 * NSPAT;
    float csum = 0.f;
#pragma unroll
    for (int c = 0; c < 5; c++) {
        float x = lg[(size_t)c * NSPAT + m];
        float p = 1.f / (1.f + __expf(-x));
        if (c == assigned) { float qq = 1.f - p; csum -= qq * qq * logsig_f(x); }
        else               {                     csum -= p * p * logsig_f(-x); }
    }

    float r = 0.f;
    if (matched < 0) {
        const float* off = out + OFFSETS_OFF + (size_t)b * 3 * NSPAT;
        int z = m >> 12, y = (m >> 6) & 63, x = m & 63;
        float pz = (z + 0.5f) * 32.f + off[m];
        float py = (y + 0.5f) * 32.f + off[NSPAT + m];
        float px = (x + 0.5f) * 32.f + off[2 * NSPAT + m];
        float dz = pz - s_gt0[0], dy = py - s_gt0[1], dx = px - s_gt0[2];
        float d = dz * dz + dy * dy + dx * dx;
        r = 1.f - __expf(-d * s_gt0[3]);
    }

    __shared__ double sd[256];
    sd[tid] = (double)csum + (double)r;
    __syncthreads();
    for (int s = 128; s > 0; s >>= 1) {
        if (tid < s) sd[tid] += sd[tid + s];
        __syncthreads();
    }
    if (tid == 0) atomicAdd(&g_loss[0], sd[0]);
}

__global__ void finalize_kernel(const void* __restrict__ nitems, float* __restrict__ out) {
    long long iv = ((const int*)nitems)[0];
    float     fv = ((const float*)nitems)[0];
    double n = (iv >= 1 && iv <= 1048576) ? (double)iv : (double)fv;
    out[LOSS_OFF] = (float)(g_loss[0] / n);
}

// ---------------------------------------------------------------------------
extern "C" void kernel_launch(void* const* d_in, const int* in_sizes, int n_in,
                              void* d_out, int out_size) {
    const float* feat   = (const float*)d_in[0];
    const float* labels = (const float*)d_in[1];
    const float* cls_w  = (const float*)d_in[2];
    const float* cls_b  = (const float*)d_in[3];
    const float* off_w  = (const float*)d_in[4];
    const float* off_b  = (const float*)d_in[5];
    float* out = (float*)d_out;

    cudaFuncSetAttribute(conv_mma_kernel, cudaFuncAttributeMaxDynamicSharedMemorySize, SM_TOTAL);

    transpose_kernel<<<dim3(64, 64, 2), 256>>>(feat);
    build_tab_kernel<<<14, 256>>>(cls_w, off_w);
    init_kernel<<<1, 256>>>();
    conv_mma_kernel<<<NBLK, 256, SM_TOTAL>>>(cls_b, off_b, out);
    best_anchor_kernel<<<dim3(256, 2), 256>>>(out, labels);
    loss_kernel<<<dim3(1024, 2), 256>>>(out, labels);
    finalize_kernel<<<1, 1>>>(d_in[6], out);
}

// round 8
// speedup vs baseline: 2.3959x; 1.2509x over previous
#include <cuda_runtime.h>
#include <cuda_fp16.h>
#include <math.h>

#define NSPAT (64*64*64)
#define OFFSETS_OFF (2*5*NSPAT)
#define LOSS_OFF (16*NSPAT)

// padded scratch: featT[b][z+1 of 66][y+1 of 66][x of 64][c of 64] fp16
// pad rows never written -> stay zero from static init
#define PD 66
__device__ __align__(16) __half g_featT[(size_t)2*PD*PD*64*64];
// B fragments: [tap(27)][kc(4)][lane(32)] -> uint2 {b0,b1} fp16x2
__device__ __align__(16) uint2 g_btab[3456];
__device__ unsigned long long g_key[128];
__device__ double g_loss[1];
__device__ unsigned g_tile;

// ---------------------------------------------------------------------------
// Pass 1: NCDHW fp32 -> padded NHWC fp16 (vectorized)
// ---------------------------------------------------------------------------
__global__ __launch_bounds__(256) void transpose_kernel(const float* __restrict__ feat) {
    __shared__ float s[64][68];
    int y = blockIdx.x, z = blockIdx.y, b = blockIdx.z;
    int tid = threadIdx.x;
    const float* base = feat + (size_t)b * 64 * NSPAT + z * 4096 + y * 64;
#pragma unroll
    for (int k = 0; k < 4; k++) {
        int i = tid + k * 256;              // 1024 float4 items
        int c = i >> 4, xg = (i & 15) * 4;
        float4 v = *(const float4*)(base + (size_t)c * NSPAT + xg);
        s[c][xg] = v.x; s[c][xg + 1] = v.y; s[c][xg + 2] = v.z; s[c][xg + 3] = v.w;
    }
    __syncthreads();
    __half* dst = g_featT + ((((size_t)b * PD + z + 1) * PD + y + 1) * 64) * 64;
#pragma unroll
    for (int k = 0; k < 2; k++) {
        int i = tid + k * 256;              // 512 items: v-row x 8-channel group
        int v = i >> 3, cg = (i & 7) * 8;
        __half2 h[4];
#pragma unroll
        for (int j = 0; j < 4; j++)
            h[j] = __floats2half2_rn(s[cg + 2 * j][v], s[cg + 2 * j + 1][v]);
        *(uint4*)(dst + v * 64 + cg) = *(uint4*)h;
    }
}

// ---------------------------------------------------------------------------
// Precompute packed fp16 B fragments once
// ---------------------------------------------------------------------------
__global__ void build_tab_kernel(const float* __restrict__ cls_w,
                                 const float* __restrict__ off_w) {
    int i = blockIdx.x * 256 + threadIdx.x;     // 0..3455
    if (i >= 3456) return;
    int l = i & 31, kc = (i >> 5) & 3, tap = i >> 7;
    int n = l >> 2, k0 = (l & 3) * 2;
    int kk = kc * 16 + k0;
    const float* w = (n < 5) ? (cls_w + n * 1728) : (off_w + (n - 5) * 1728);
    uint2 r;
    r.x = (unsigned)__half_as_ushort(__float2half_rn(w[kk * 27 + tap]))
        | ((unsigned)__half_as_ushort(__float2half_rn(w[(kk + 1) * 27 + tap])) << 16);
    r.y = (unsigned)__half_as_ushort(__float2half_rn(w[(kk + 8) * 27 + tap]))
        | ((unsigned)__half_as_ushort(__float2half_rn(w[(kk + 9) * 27 + tap])) << 16);
    g_btab[i] = r;
}

// ---------------------------------------------------------------------------
// Pass 2: persistent fp16 conv, shift-accumulator trick (1 ldmatrix / kc)
// ---------------------------------------------------------------------------
__device__ __forceinline__ void writeOut(float* out, int b, int n, int m, float v) {
    if (n < 5) out[(size_t)(b * 5 + n) * NSPAT + m] = v;
    else       out[OFFSETS_OFF + (size_t)(b * 3 + (n - 5)) * NSPAT + m] = v;
}

#define MMA_F16(ac, a0,a1,a2,a3, b0,b1) \
    asm volatile("mma.sync.aligned.m16n8k16.row.col.f32.f16.f16.f32 " \
        "{%0,%1,%2,%3}, {%4,%5,%6,%7}, {%8,%9}, {%0,%1,%2,%3};" \
        : "+f"(ac[0]), "+f"(ac[1]), "+f"(ac[2]), "+f"(ac[3]) \
        : "r"(a0), "r"(a1), "r"(a2), "r"(a3), "r"(b0), "r"(b1))

#define SM_BUF 8192                 /* 64 voxels * 64ch * 2B */
#define SM_TAB (3*SM_BUF)           /* 24576 */
#define SM_EDGE (SM_TAB + 27648)    /* 52224: sPe 1KB, sMe 1KB */
#define SM_TOTAL (SM_EDGE + 2048 + 16)
#define NTILES 1024
#define NBLK 296
#define FULLM 0xFFFFFFFFu

extern __shared__ unsigned char s_dyn[];

__global__ __launch_bounds__(256) void conv_mma_kernel(
        const float* __restrict__ cls_b, const float* __restrict__ off_b,
        float* __restrict__ out) {
    int tid = threadIdx.x, lane = tid & 31, warp = tid >> 5;
    int q = warp & 3, riL = warp >> 2;

    unsigned sbase = (unsigned)__cvta_generic_to_shared(s_dyn);
    const uint2* s_tab = (const uint2*)(s_dyn + SM_TAB);
    float* sPe = (float*)(s_dyn + SM_EDGE);          // [s][riL][q][j][2]
    float* sMe = (float*)(s_dyn + SM_EDGE + 1024);
    unsigned* s_tile = (unsigned*)(s_dyn + SM_EDGE + 2048);

    {
        uint2* dst = (uint2*)(s_dyn + SM_TAB);
        for (int i = tid; i < 3456; i += 256) dst[i] = g_btab[i];
    }

    int n0 = (lane & 3) * 2;
    float bi0 = (n0 < 5)     ? cls_b[n0]     : off_b[n0 - 5];
    float bi1 = (n0 + 1 < 5) ? cls_b[n0 + 1] : off_b[n0 - 4];

    for (;;) {
        if (tid == 0) s_tile[0] = atomicAdd(&g_tile, 1u);
        __syncthreads();
        unsigned t = s_tile[0];
        if (t >= NTILES) break;

        int z0 = (t & 31) * 2;
        int y0 = ((t >> 5) & 15) * 4;
        int b  = t >> 9;

        // acc[slot][shift(P,C,M)][4]; bias only in center
        float acc[4][3][4];
#pragma unroll
        for (int s = 0; s < 4; s++) {
#pragma unroll
            for (int j = 0; j < 3; j++) {
                float v0 = (j == 1) ? bi0 : 0.f, v1 = (j == 1) ? bi1 : 0.f;
                acc[s][j][0] = v0; acc[s][j][1] = v1; acc[s][j][2] = v0; acc[s][j][3] = v1;
            }
        }

#define ISSUE_LOAD(ZZ_, YY_, BUF_) do { \
    const uint4* src_ = (const uint4*)(g_featT + \
        ((((size_t)b * PD + (z0 + (ZZ_))) * PD + (y0 + (YY_))) * 64) * 64); \
    unsigned dbase_ = sbase + (BUF_) * SM_BUF; \
    _Pragma("unroll") \
    for (int k_ = 0; k_ < 2; k_++) { \
        int i_ = tid + k_ * 256; int v_ = i_ >> 3, ch_ = i_ & 7; \
        unsigned d_ = dbase_ + (unsigned)((v_ * 8 + (ch_ ^ (v_ & 7))) * 16); \
        asm volatile("cp.async.cg.shared.global [%0], [%1], 16;" :: "r"(d_), "l"(src_ + i_)); \
    } \
    asm volatile("cp.async.commit_group;"); \
} while (0)

        ISSUE_LOAD(0, 0, 0);
        ISSUE_LOAD(0, 1, 1);

#pragma unroll 1
        for (int zz = 0; zz < 4; zz++) {
#pragma unroll
            for (int yy = 0; yy < 6; yy++) {
                if (zz == 3 && yy == 5) asm volatile("cp.async.wait_group 0;");
                else                    asm volatile("cp.async.wait_group 1;");
                __syncthreads();
                if (!(zz == 3 && yy >= 4)) {
                    if (yy < 4) ISSUE_LOAD(zz,     yy + 2, (yy + 2) % 3);
                    else        ISSUE_LOAD(zz + 1, yy - 4, (yy + 2) % 3);
                }

                bool active = riL ? (yy >= 1) : (yy <= 4);
                if (active) {
                    unsigned abase = sbase + (unsigned)((yy % 3) * SM_BUF);
#pragma unroll
                    for (int kc = 0; kc < 4; kc++) {
                        int vs = 16 * q + (lane & 15);
                        int chunk = 2 * kc + (lane >> 4);
                        unsigned aAddr = abase + (unsigned)((vs * 8 + (chunk ^ (vs & 7))) * 16);
                        unsigned a0, a1, a2, a3;
                        asm volatile("ldmatrix.sync.aligned.m8n8.x4.shared.b16 {%0,%1,%2,%3}, [%4];"
                            : "=r"(a0), "=r"(a1), "=r"(a2), "=r"(a3) : "r"(aAddr));
#pragma unroll
                        for (int zi = 0; zi < 2; zi++) {
                            unsigned dz = (unsigned)(zz - zi);
                            if (dz > 2u) continue;
#pragma unroll
                            for (int rih = 0; rih < 2; rih++) {
                                int y = rih * 2 + riL;
                                unsigned dy = (unsigned)(yy - y);
                                if (dy > 2u) continue;
                                int tb = (int)(dz * 9u + dy * 3u);
#pragma unroll
                                for (int dx = 0; dx < 3; dx++) {
                                    uint2 B = s_tab[((tb + dx) * 4 + kc) * 32 + lane];
                                    MMA_F16(acc[zi * 2 + rih][dx], a0, a1, a2, a3, B.x, B.y);
                                }
                            }
                        }
                    }
                }
            }
        }
        __syncthreads();

        // stage cross-warp boundary values (x-edges of each 16-voxel segment)
        int j = lane & 3;
#pragma unroll
        for (int s = 0; s < 4; s++) {
            int e = ((s * 2 + riL) * 4 + q) * 8 + j * 2;
            if (lane >= 28) { sPe[e] = acc[s][0][2]; sPe[e + 1] = acc[s][0][3]; } // P row15
            if (lane < 4)   { sMe[e] = acc[s][2][0]; sMe[e + 1] = acc[s][2][1]; } // M row0
        }
        __syncthreads();

#pragma unroll
        for (int s = 0; s < 4; s++) {
            float* P = acc[s][0]; float* C = acc[s][1]; float* M = acc[s][2];
            // P shifted +1 row
            float p0s = __shfl_up_sync(FULLM, P[0], 4);
            float p1s = __shfl_up_sync(FULLM, P[1], 4);
            float p2s = __shfl_up_sync(FULLM, P[2], 4);
            float p3s = __shfl_up_sync(FULLM, P[3], 4);
            float p0h = __shfl_sync(FULLM, P[0], 28 + j);
            float p1h = __shfl_sync(FULLM, P[1], 28 + j);
            // M shifted -1 row
            float m0s = __shfl_down_sync(FULLM, M[0], 4);
            float m1s = __shfl_down_sync(FULLM, M[1], 4);
            float m2s = __shfl_down_sync(FULLM, M[2], 4);
            float m3s = __shfl_down_sync(FULLM, M[3], 4);
            float m2h = __shfl_sync(FULLM, M[2], j);
            float m3h = __shfl_sync(FULLM, M[3], j);
            if (lane < 4) {
                p2s = p0h; p3s = p1h;                       // row8 <- row7
                int e = ((s * 2 + riL) * 4 + (q - 1)) * 8 + j * 2;
                p0s = (q > 0) ? sPe[e]     : 0.f;           // row0 <- warp q-1 row15
                p1s = (q > 0) ? sPe[e + 1] : 0.f;
            }
            if (lane >= 28) {
                int jj = lane - 28;
                m0s = m2h; m1s = m3h;                       // row7 <- row8
                int e = ((s * 2 + riL) * 4 + (q + 1)) * 8 + jj * 2;
                m2s = (q < 3) ? sMe[e]     : 0.f;           // row15 <- warp q+1 row0
                m3s = (q < 3) ? sMe[e + 1] : 0.f;
            }
            float d0 = C[0] + p0s + m0s;
            float d1 = C[1] + p1s + m1s;
            float d2 = C[2] + p2s + m2s;
            float d3 = C[3] + p3s + m3s;

            int zi = s >> 1, ri = (s & 1) * 2 + riL;
            int mg = (z0 + zi) * 4096 + (y0 + ri) * 64 + 16 * q + (lane >> 2);
            writeOut(out, b, n0,     mg,     d0);
            writeOut(out, b, n0 + 1, mg,     d1);
            writeOut(out, b, n0,     mg + 8, d2);
            writeOut(out, b, n0 + 1, mg + 8, d3);
        }
    }
}

// ---------------------------------------------------------------------------
// Best anchor per GT: argmin(d) with u64 (d_bits<<32|idx) atomicMin
// ---------------------------------------------------------------------------
__global__ void init_kernel() {
    int t = threadIdx.x;
    if (t < 128) g_key[t] = 0xFFFFFFFFFFFFFFFFull;
    if (t == 128) g_loss[0] = 0.0;
    if (t == 129) g_tile = 0u;
}

__global__ __launch_bounds__(256) void best_anchor_kernel(const float* __restrict__ out,
                                                          const float* __restrict__ labels) {
    int b = blockIdx.y, tid = threadIdx.x, lane = tid & 31, warp = tid >> 5;
    int base = blockIdx.x * 1024;
    const float* off = out + OFFSETS_OFF + (size_t)b * 3 * NSPAT;

    float pz[4], py[4], px[4];
#pragma unroll
    for (int i = 0; i < 4; i++) {
        int m = base + i * 256 + tid;
        int zc = m >> 12, yc = (m >> 6) & 63, xc = m & 63;
        pz[i] = (zc + 0.5f) * 32.f + off[m];
        py[i] = (yc + 0.5f) * 32.f + off[NSPAT + m];
        px[i] = (xc + 0.5f) * 32.f + off[2 * NSPAT + m];
    }
    __shared__ float sc[3][64];
    __shared__ unsigned long long s_red[64][8];
    if (tid < 192) { int d = tid >> 6, n = tid & 63; sc[d][n] = labels[(b * 5 + d) * 64 + n]; }
    __syncthreads();

    for (int n = 0; n < 64; n++) {
        float tz = sc[0][n], ty = sc[1][n], tx = sc[2][n];
        unsigned long long best = 0xFFFFFFFFFFFFFFFFull;
#pragma unroll
        for (int i = 0; i < 4; i++) {
            float dz = pz[i] - tz, dy = py[i] - ty, dx = px[i] - tx;
            float d = dz * dz + dy * dy + dx * dx;
            unsigned long long key = ((unsigned long long)__float_as_uint(d) << 32)
                                   | (unsigned)(base + i * 256 + tid);
            best = min(best, key);
        }
#pragma unroll
        for (int s = 16; s; s >>= 1)
            best = min(best, __shfl_down_sync(0xFFFFFFFFu, best, s));
        if (lane == 0) s_red[n][warp] = best;
    }
    __syncthreads();
    if (tid < 64) {
        unsigned long long best = s_red[tid][0];
#pragma unroll
        for (int w = 1; w < 8; w++) best = min(best, s_red[tid][w]);
        atomicMin(&g_key[b * 64 + tid], best);
    }
}

// ---------------------------------------------------------------------------
// Focal + reg loss (fast-math transcendentals; double accumulation)
// ---------------------------------------------------------------------------
__device__ __forceinline__ float logsig_f(float x) {
    return fminf(x, 0.f) - __logf(1.f + __expf(-fabsf(x)));
}

__global__ __launch_bounds__(256) void loss_kernel(const float* __restrict__ out,
                                                   const float* __restrict__ labels) {
    int b = blockIdx.y, tid = threadIdx.x;
    int m0 = blockIdx.x * 256, m = m0 + tid;

    __shared__ int   s_match[256];
    __shared__ float s_gt0[4];
    s_match[tid] = -1;
    __syncthreads();
    if (tid < 64) {
        float c = labels[(b * 5 + 3) * 64 + tid];
        if (c >= -0.5f) {
            int bm = (int)(unsigned)(g_key[b * 64 + tid] & 0xFFFFFFFFull);
            if (bm >= m0 && bm < m0 + 256) atomicMax(&s_match[bm - m0], tid);
        }
    }
    if (tid == 128) {
        float sg = labels[(b * 5 + 4) * 64];
        s_gt0[0] = labels[(b * 5 + 0) * 64];
        s_gt0[1] = labels[(b * 5 + 1) * 64];
        s_gt0[2] = labels[(b * 5 + 2) * 64];
        s_gt0[3] = 1.f / (2.f * sg * sg);
    }
    __syncthreads();

    int matched = s_match[tid];
    int assigned = (matched >= 0) ? (int)labels[(b * 5 + 3) * 64 + matched] : -1;

    const float* lg = out + (size_t)b * 5 * NSPAT;
    float csum = 0.f;
#pragma unroll
    for (int c = 0; c < 5; c++) {
        float x = lg[(size_t)c * NSPAT + m];
        float p = 1.f / (1.f + __expf(-x));
        if (c == assigned) { float qq = 1.f - p; csum -= qq * qq * logsig_f(x); }
        else               {                     csum -= p * p * logsig_f(-x); }
    }

    float r = 0.f;
    if (matched < 0) {
        const float* off = out + OFFSETS_OFF + (size_t)b * 3 * NSPAT;
        int z = m >> 12, y = (m >> 6) & 63, x = m & 63;
        float pz = (z + 0.5f) * 32.f + off[m];
        float py = (y + 0.5f) * 32.f + off[NSPAT + m];
        float px = (x + 0.5f) * 32.f + off[2 * NSPAT + m];
        float dz = pz - s_gt0[0], dy = py - s_gt0[1], dx = px - s_gt0[2];
        float d = dz * dz + dy * dy + dx * dx;
        r = 1.f - __expf(-d * s_gt0[3]);
    }

    __shared__ double sd[256];
    sd[tid] = (double)csum + (double)r;
    __syncthreads();
    for (int s = 128; s > 0; s >>= 1) {
        if (tid < s) sd[tid] += sd[tid + s];
        __syncthreads();
    }
    if (tid == 0) atomicAdd(&g_loss[0], sd[0]);
}

__global__ void finalize_kernel(const void* __restrict__ nitems, float* __restrict__ out) {
    long long iv = ((const int*)nitems)[0];
    float     fv = ((const float*)nitems)[0];
    double n = (iv >= 1 && iv <= 1048576) ? (double)iv : (double)fv;
    out[LOSS_OFF] = (float)(g_loss[0] / n);
}

// ---------------------------------------------------------------------------
extern "C" void kernel_launch(void* const* d_in, const int* in_sizes, int n_in,
                              void* d_out, int out_size) {
    const float* feat   = (const float*)d_in[0];
    const float* labels = (const float*)d_in[1];
    const float* cls_w  = (const float*)d_in[2];
    const float* cls_b  = (const float*)d_in[3];
    const float* off_w  = (const float*)d_in[4];
    const float* off_b  = (const float*)d_in[5];
    float* out = (float*)d_out;

    cudaFuncSetAttribute(conv_mma_kernel, cudaFuncAttributeMaxDynamicSharedMemorySize, SM_TOTAL);

    transpose_kernel<<<dim3(64, 64, 2), 256>>>(feat);
    build_tab_kernel<<<14, 256>>>(cls_w, off_w);
    init_kernel<<<1, 256>>>();
    conv_mma_kernel<<<NBLK, 256, SM_TOTAL>>>(cls_b, off_b, out);
    best_anchor_kernel<<<dim3(256, 2), 256>>>(out, labels);
    loss_kernel<<<dim3(1024, 2), 256>>>(out, labels);
    finalize_kernel<<<1, 1>>>(d_in[6], out);
}

// round 9
// speedup vs baseline: 2.7282x; 1.1387x over previous
#include <cuda_runtime.h>
#include <cuda_fp16.h>
#include <math.h>

#define NSPAT (64*64*64)
#define OFFSETS_OFF (2*5*NSPAT)
#define LOSS_OFF (16*NSPAT)

// B fragments: [tap(27)][kcp(2)][lane(32)] -> uint4 {kc lo,hi | kc+1 lo,hi}
__device__ __align__(16) uint4 g_btab[1728];
__device__ unsigned long long g_key[128];
__device__ double g_loss[1];
__device__ unsigned g_tile;

// ---------------------------------------------------------------------------
// Precompute packed fp16 B fragments once
// ---------------------------------------------------------------------------
__global__ void build_tab_kernel(const float* __restrict__ cls_w,
                                 const float* __restrict__ off_w) {
    int i = blockIdx.x * 256 + threadIdx.x;     // 0..1727
    if (i >= 1728) return;
    int lane = i & 31, kcp = (i >> 5) & 1, tap = i >> 6;
    int n = lane >> 2, k0 = (lane & 3) * 2;
    const float* w = (n < 5) ? (cls_w + n * 1728) : (off_w + (n - 5) * 1728);
    uint4 r;
    {
        int kk = (2 * kcp) * 16 + k0;
        r.x = (unsigned)__half_as_ushort(__float2half_rn(w[kk * 27 + tap]))
            | ((unsigned)__half_as_ushort(__float2half_rn(w[(kk + 1) * 27 + tap])) << 16);
        r.y = (unsigned)__half_as_ushort(__float2half_rn(w[(kk + 8) * 27 + tap]))
            | ((unsigned)__half_as_ushort(__float2half_rn(w[(kk + 9) * 27 + tap])) << 16);
    }
    {
        int kk = (2 * kcp + 1) * 16 + k0;
        r.z = (unsigned)__half_as_ushort(__float2half_rn(w[kk * 27 + tap]))
            | ((unsigned)__half_as_ushort(__float2half_rn(w[(kk + 1) * 27 + tap])) << 16);
        r.w = (unsigned)__half_as_ushort(__float2half_rn(w[(kk + 8) * 27 + tap]))
            | ((unsigned)__half_as_ushort(__float2half_rn(w[(kk + 9) * 27 + tap])) << 16);
    }
    g_btab[i] = r;
}

// ---------------------------------------------------------------------------
// Fused conv: direct fp32 NCDHW load + fp16 convert + shift-accumulator MMA
// ---------------------------------------------------------------------------
__device__ __forceinline__ void writeOut(float* out, int b, int n, int m, float v) {
    if (n < 5) out[(size_t)(b * 5 + n) * NSPAT + m] = v;
    else       out[OFFSETS_OFF + (size_t)(b * 3 + (n - 5)) * NSPAT + m] = v;
}

#define MMA_F16(ac, a0,a1,a2,a3, b0,b1) \
    asm volatile("mma.sync.aligned.m16n8k16.row.col.f32.f16.f16.f32 " \
        "{%0,%1,%2,%3}, {%4,%5,%6,%7}, {%8,%9}, {%0,%1,%2,%3};" \
        : "+f"(ac[0]), "+f"(ac[1]), "+f"(ac[2]), "+f"(ac[3]) \
        : "r"(a0), "r"(a1), "r"(a2), "r"(a3), "r"(b0), "r"(b1))

#define SM_BUF 8192                 /* 64 voxels * 64ch * 2B */
#define SM_TAB (3*SM_BUF)           /* 24576 */
#define SM_EDGE (SM_TAB + 27648)    /* 52224 */
#define SM_TOTAL (SM_EDGE + 2048 + 16)
#define NTILES 1024
#define NBLK 296
#define FULLM 0xFFFFFFFFu

extern __shared__ unsigned char s_dyn[];

__global__ __launch_bounds__(256, 2) void conv_mma_kernel(
        const float* __restrict__ feat,
        const float* __restrict__ cls_b, const float* __restrict__ off_b,
        float* __restrict__ out) {
    int tid = threadIdx.x, lane = tid & 31, warp = tid >> 5;
    int q = warp & 3, riL = warp >> 2;

    unsigned sbase = (unsigned)__cvta_generic_to_shared(s_dyn);
    const uint4* s_tab = (const uint4*)(s_dyn + SM_TAB);
    float* sPe = (float*)(s_dyn + SM_EDGE);
    float* sMe = (float*)(s_dyn + SM_EDGE + 1024);
    unsigned* s_tile = (unsigned*)(s_dyn + SM_EDGE + 2048);

    {
        uint4* dst = (uint4*)(s_dyn + SM_TAB);
        for (int i = tid; i < 1728; i += 256) dst[i] = g_btab[i];
    }

    int n0 = (lane & 3) * 2;
    float bi0 = (n0 < 5)     ? cls_b[n0]     : off_b[n0 - 5];
    float bi1 = (n0 + 1 < 5) ? cls_b[n0 + 1] : off_b[n0 - 4];

    // each lane loads x = 2*lane, 2*lane+1 for channels warp*8..warp*8+7
    const float* featW = feat + (size_t)(warp * 8) * NSPAT + 2 * lane;

#define LDG_ROW(ZZ_, YY_, RR_) do { \
    int zp_ = z0 + (ZZ_) - 1, yp_ = y0 + (YY_) - 1; \
    if (((unsigned)zp_ < 64u) & ((unsigned)yp_ < 64u)) { \
        const float* p_ = featW + (size_t)b * 64 * NSPAT + zp_ * 4096 + yp_ * 64; \
        _Pragma("unroll") \
        for (int cc_ = 0; cc_ < 8; cc_++) RR_[cc_] = *(const float2*)(p_ + (size_t)cc_ * NSPAT); \
    } else { \
        _Pragma("unroll") \
        for (int cc_ = 0; cc_ < 8; cc_++) RR_[cc_] = make_float2(0.f, 0.f); \
    } \
} while (0)

#define STS_ROW(BUF_, RR_) do { \
    __half2 h0_[4], h1_[4]; \
    _Pragma("unroll") \
    for (int j_ = 0; j_ < 4; j_++) { \
        h0_[j_] = __floats2half2_rn(RR_[2*j_].x, RR_[2*j_+1].x); \
        h1_[j_] = __floats2half2_rn(RR_[2*j_].y, RR_[2*j_+1].y); \
    } \
    int v0_ = 2 * lane, v1_ = 2 * lane + 1; \
    *(uint4*)(s_dyn + (BUF_) * SM_BUF + (v0_ * 8 + (warp ^ (v0_ & 7))) * 16) = *(uint4*)h0_; \
    *(uint4*)(s_dyn + (BUF_) * SM_BUF + (v1_ * 8 + (warp ^ (v1_ & 7))) * 16) = *(uint4*)h1_; \
} while (0)

    for (;;) {
        if (tid == 0) s_tile[0] = atomicAdd(&g_tile, 1u);
        __syncthreads();
        unsigned t = s_tile[0];
        if (t >= NTILES) break;

        int z0 = (t & 31) * 2;
        int y0 = ((t >> 5) & 15) * 4;
        int b  = t >> 9;

        float acc[4][3][4];
#pragma unroll
        for (int s = 0; s < 4; s++)
#pragma unroll
            for (int j = 0; j < 3; j++) {
                float v0 = (j == 1) ? bi0 : 0.f, v1 = (j == 1) ? bi1 : 0.f;
                acc[s][j][0] = v0; acc[s][j][1] = v1; acc[s][j][2] = v0; acc[s][j][3] = v1;
            }

        float2 rA[8], rB[8];
        // preamble: rows 0,1 -> buf0,buf1; row2 held in rA (even row -> bank A)
        LDG_ROW(0, 0, rA);
        LDG_ROW(0, 1, rB);
        STS_ROW(0, rA);
        STS_ROW(1, rB);
        LDG_ROW(0, 2, rA);

#pragma unroll 1
        for (int zz = 0; zz < 4; zz++) {
#pragma unroll
            for (int yy = 0; yy < 6; yy++) {
                __syncthreads();
                // STS row i+2 (bank = yy&1), LDG row i+3 (bank = (yy+1)&1)
                if (!(zz == 3 && yy >= 4)) {
                    if (yy & 1) STS_ROW((yy + 2) % 3, rB);
                    else        STS_ROW((yy + 2) % 3, rA);
                }
                if (!(zz == 3 && yy >= 3)) {
                    if (yy & 1) { if (yy + 3 < 6) LDG_ROW(zz, yy + 3, rA); else LDG_ROW(zz + 1, yy - 3, rA); }
                    else        { if (yy + 3 < 6) LDG_ROW(zz, yy + 3, rB); else LDG_ROW(zz + 1, yy - 3, rB); }
                }

                bool active = riL ? (yy >= 1) : (yy <= 4);
                if (active) {
                    unsigned abase = sbase + (unsigned)((yy % 3) * SM_BUF);
#pragma unroll
                    for (int kcp = 0; kcp < 2; kcp++) {
                        int vs = 16 * q + (lane & 15);
                        unsigned ch0 = (unsigned)(4 * kcp + (lane >> 4));
                        unsigned ch1 = ch0 + 2;
                        unsigned adr0 = abase + (unsigned)((vs * 8 + (ch0 ^ (vs & 7))) * 16);
                        unsigned adr1 = abase + (unsigned)((vs * 8 + (ch1 ^ (vs & 7))) * 16);
                        unsigned a0, a1, a2, a3, c0, c1, c2, c3;
                        asm volatile("ldmatrix.sync.aligned.m8n8.x4.shared.b16 {%0,%1,%2,%3}, [%4];"
                            : "=r"(a0), "=r"(a1), "=r"(a2), "=r"(a3) : "r"(adr0));
                        asm volatile("ldmatrix.sync.aligned.m8n8.x4.shared.b16 {%0,%1,%2,%3}, [%4];"
                            : "=r"(c0), "=r"(c1), "=r"(c2), "=r"(c3) : "r"(adr1));
#pragma unroll
                        for (int zi = 0; zi < 2; zi++) {
                            unsigned dz = (unsigned)(zz - zi);
                            if (dz > 2u) continue;
#pragma unroll
                            for (int rih = 0; rih < 2; rih++) {
                                int y = rih * 2 + riL;
                                unsigned dy = (unsigned)(yy - y);
                                if (dy > 2u) continue;
                                int tb = (int)(dz * 9u + dy * 3u);
#pragma unroll
                                for (int dx = 0; dx < 3; dx++) {
                                    uint4 B = s_tab[((tb + dx) * 2 + kcp) * 32 + lane];
                                    MMA_F16(acc[zi * 2 + rih][dx], a0, a1, a2, a3, B.x, B.y);
                                    MMA_F16(acc[zi * 2 + rih][dx], c0, c1, c2, c3, B.z, B.w);
                                }
                            }
                        }
                    }
                }
            }
        }
        __syncthreads();

        // stage cross-warp boundary values
        int j = lane & 3;
#pragma unroll
        for (int s = 0; s < 4; s++) {
            int e = ((s * 2 + riL) * 4 + q) * 8 + j * 2;
            if (lane >= 28) { sPe[e] = acc[s][0][2]; sPe[e + 1] = acc[s][0][3]; }
            if (lane < 4)   { sMe[e] = acc[s][2][0]; sMe[e + 1] = acc[s][2][1]; }
        }
        __syncthreads();

#pragma unroll
        for (int s = 0; s < 4; s++) {
            float* P = acc[s][0]; float* C = acc[s][1]; float* M = acc[s][2];
            float p0s = __shfl_up_sync(FULLM, P[0], 4);
            float p1s = __shfl_up_sync(FULLM, P[1], 4);
            float p2s = __shfl_up_sync(FULLM, P[2], 4);
            float p3s = __shfl_up_sync(FULLM, P[3], 4);
            float p0h = __shfl_sync(FULLM, P[0], 28 + j);
            float p1h = __shfl_sync(FULLM, P[1], 28 + j);
            float m0s = __shfl_down_sync(FULLM, M[0], 4);
            float m1s = __shfl_down_sync(FULLM, M[1], 4);
            float m2s = __shfl_down_sync(FULLM, M[2], 4);
            float m3s = __shfl_down_sync(FULLM, M[3], 4);
            float m2h = __shfl_sync(FULLM, M[2], j);
            float m3h = __shfl_sync(FULLM, M[3], j);
            if (lane < 4) {
                p2s = p0h; p3s = p1h;
                int e = ((s * 2 + riL) * 4 + (q - 1)) * 8 + j * 2;
                p0s = (q > 0) ? sPe[e]     : 0.f;
                p1s = (q > 0) ? sPe[e + 1] : 0.f;
            }
            if (lane >= 28) {
                int jj = lane - 28;
                m0s = m2h; m1s = m3h;
                int e = ((s * 2 + riL) * 4 + (q + 1)) * 8 + jj * 2;
                m2s = (q < 3) ? sMe[e]     : 0.f;
                m3s = (q < 3) ? sMe[e + 1] : 0.f;
            }
            float d0 = C[0] + p0s + m0s;
            float d1 = C[1] + p1s + m1s;
            float d2 = C[2] + p2s + m2s;
            float d3 = C[3] + p3s + m3s;

            int zi = s >> 1, ri = (s & 1) * 2 + riL;
            int mg = (z0 + zi) * 4096 + (y0 + ri) * 64 + 16 * q + (lane >> 2);
            writeOut(out, b, n0,     mg,     d0);
            writeOut(out, b, n0 + 1, mg,     d1);
            writeOut(out, b, n0,     mg + 8, d2);
            writeOut(out, b, n0 + 1, mg + 8, d3);
        }
    }
}

// ---------------------------------------------------------------------------
// Best anchor per GT: argmin(d) with u64 (d_bits<<32|idx) atomicMin
// ---------------------------------------------------------------------------
__global__ void init_kernel() {
    int t = threadIdx.x;
    if (t < 128) g_key[t] = 0xFFFFFFFFFFFFFFFFull;
    if (t == 128) g_loss[0] = 0.0;
    if (t == 129) g_tile = 0u;
}

__global__ __launch_bounds__(256) void best_anchor_kernel(const float* __restrict__ out,
                                                          const float* __restrict__ labels) {
    int b = blockIdx.y, tid = threadIdx.x, lane = tid & 31, warp = tid >> 5;
    int base = blockIdx.x * 1024;
    const float* off = out + OFFSETS_OFF + (size_t)b * 3 * NSPAT;

    float pz[4], py[4], px[4];
#pragma unroll
    for (int i = 0; i < 4; i++) {
        int m = base + i * 256 + tid;
        int zc = m >> 12, yc = (m >> 6) & 63, xc = m & 63;
        pz[i] = (zc + 0.5f) * 32.f + off[m];
        py[i] = (yc + 0.5f) * 32.f + off[NSPAT + m];
        px[i] = (xc + 0.5f) * 32.f + off[2 * NSPAT + m];
    }
    __shared__ float sc[3][64];
    __shared__ unsigned long long s_red[64][8];
    if (tid < 192) { int d = tid >> 6, n = tid & 63; sc[d][n] = labels[(b * 5 + d) * 64 + n]; }
    __syncthreads();

    for (int n = 0; n < 64; n++) {
        float tz = sc[0][n], ty = sc[1][n], tx = sc[2][n];
        unsigned long long best = 0xFFFFFFFFFFFFFFFFull;
#pragma unroll
        for (int i = 0; i < 4; i++) {
            float dz = pz[i] - tz, dy = py[i] - ty, dx = px[i] - tx;
            float d = dz * dz + dy * dy + dx * dx;
            unsigned long long key = ((unsigned long long)__float_as_uint(d) << 32)
                                   | (unsigned)(base + i * 256 + tid);
            best = min(best, key);
        }
#pragma unroll
        for (int s = 16; s; s >>= 1)
            best = min(best, __shfl_down_sync(0xFFFFFFFFu, best, s));
        if (lane == 0) s_red[n][warp] = best;
    }
    __syncthreads();
    if (tid < 64) {
        unsigned long long best = s_red[tid][0];
#pragma unroll
        for (int w = 1; w < 8; w++) best = min(best, s_red[tid][w]);
        atomicMin(&g_key[b * 64 + tid], best);
    }
}

// ---------------------------------------------------------------------------
// Focal + reg loss (fast-math transcendentals; double accumulation)
// ---------------------------------------------------------------------------
__device__ __forceinline__ float logsig_f(float x) {
    return fminf(x, 0.f) - __logf(1.f + __expf(-fabsf(x)));
}

__global__ __launch_bounds__(256) void loss_kernel(const float* __restrict__ out,
                                                   const float* __restrict__ labels) {
    int b = blockIdx.y, tid = threadIdx.x;
    int m0 = blockIdx.x * 256, m = m0 + tid;

    __shared__ int   s_match[256];
    __shared__ float s_gt0[4];
    s_match[tid] = -1;
    __syncthreads();
    if (tid < 64) {
        float c = labels[(b * 5 + 3) * 64 + tid];
        if (c >= -0.5f) {
            int bm = (int)(unsigned)(g_key[b * 64 + tid] & 0xFFFFFFFFull);
            if (bm >= m0 && bm < m0 + 256) atomicMax(&s_match[bm - m0], tid);
        }
    }
    if (tid == 128) {
        float sg = labels[(b * 5 + 4) * 64];
        s_gt0[0] = labels[(b * 5 + 0) * 64];
        s_gt0[1] = labels[(b * 5 + 1) * 64];
        s_gt0[2] = labels[(b * 5 + 2) * 64];
        s_gt0[3] = 1.f / (2.f * sg * sg);
    }
    __syncthreads();

    int matched = s_match[tid];
    int assigned = (matched >= 0) ? (int)labels[(b * 5 + 3) * 64 + matched] : -1;

    const float* lg = out + (size_t)b * 5 * NSPAT;
    float csum = 0.f;
#pragma unroll
    for (int c = 0; c < 5; c++) {
        float x = lg[(size_t)c * NSPAT + m];
        float p = 1.f / (1.f + __expf(-x));
        if (c == assigned) { float qq = 1.f - p; csum -= qq * qq * logsig_f(x); }
        else               {                     csum -= p * p * logsig_f(-x); }
    }

    float r = 0.f;
    if (matched < 0) {
        const float* off = out + OFFSETS_OFF + (size_t)b * 3 * NSPAT;
        int z = m >> 12, y = (m >> 6) & 63, x = m & 63;
        float pz = (z + 0.5f) * 32.f + off[m];
        float py = (y + 0.5f) * 32.f + off[NSPAT + m];
        float px = (x + 0.5f) * 32.f + off[2 * NSPAT + m];
        float dz = pz - s_gt0[0], dy = py - s_gt0[1], dx = px - s_gt0[2];
        float d = dz * dz + dy * dy + dx * dx;
        r = 1.f - __expf(-d * s_gt0[3]);
    }

    __shared__ double sd[256];
    sd[tid] = (double)csum + (double)r;
    __syncthreads();
    for (int s = 128; s > 0; s >>= 1) {
        if (tid < s) sd[tid] += sd[tid + s];
        __syncthreads();
    }
    if (tid == 0) atomicAdd(&g_loss[0], sd[0]);
}

__global__ void finalize_kernel(const void* __restrict__ nitems, float* __restrict__ out) {
    long long iv = ((const int*)nitems)[0];
    float     fv = ((const float*)nitems)[0];
    double n = (iv >= 1 && iv <= 1048576) ? (double)iv : (double)fv;
    out[LOSS_OFF] = (float)(g_loss[0] / n);
}

// ---------------------------------------------------------------------------
extern "C" void kernel_launch(void* const* d_in, const int* in_sizes, int n_in,
                              void* d_out, int out_size) {
    const float* feat   = (const float*)d_in[0];
    const float* labels = (const float*)d_in[1];
    const float* cls_w  = (const float*)d_in[2];
    const float* cls_b  = (const float*)d_in[3];
    const float* off_w  = (const float*)d_in[4];
    const float* off_b  = (const float*)d_in[5];
    float* out = (float*)d_out;

    cudaFuncSetAttribute(conv_mma_kernel, cudaFuncAttributeMaxDynamicSharedMemorySize, SM_TOTAL);

    build_tab_kernel<<<7, 256>>>(cls_w, off_w);
    init_kernel<<<1, 256>>>();
    conv_mma_kernel<<<NBLK, 256, SM_TOTAL>>>(feat, cls_b, off_b, out);
    best_anchor_kernel<<<dim3(256, 2), 256>>>(out, labels);
    loss_kernel<<<dim3(1024, 2), 256>>>(out, labels);
    finalize_kernel<<<1, 1>>>(d_in[6], out);
}